// round 1
// baseline (speedup 1.0000x reference)
#include <cuda_runtime.h>
#include <math.h>

#define BATCH 32
#define SH 96
#define SW 128
#define BH 768
#define BW 1024
#define KTAPS 49
#define PAD 24
#define SSTRIDE 129   // padded smem row stride (odd -> conflict-free column access)

__device__ float d_small[BATCH * SH * SW];
__device__ float d_lse[BATCH];

// One block per batch. Loads readout tile to smem, separable 49-tap blur with
// edge clamping, adds center-bias sample, computes logsumexp on the small grid.
__global__ __launch_bounds__(512, 1)
void blur_kernel(const float* __restrict__ readout,
                 const float* __restrict__ centerbias,
                 const float* __restrict__ sf,
                 const int*   __restrict__ dsidx,
                 const float* __restrict__ sigmas,
                 const float* __restrict__ cbws,
                 const float* __restrict__ pss,
                 int n_ds)
{
    extern __shared__ float smem[];
    float* s_in   = smem;                     // SH * SSTRIDE
    float* s_tmp  = smem + SH * SSTRIDE;      // SH * SSTRIDE
    float* s_kern = s_tmp + SH * SSTRIDE;     // 64 (49 used)
    float* s_red  = s_kern + 64;              // 32
    float* s_scal = s_red + 32;               // [0]=prio [1]=cbw [2]=bmax

    const int b   = blockIdx.x;
    const int tid = threadIdx.x;
    const int wid = tid >> 5;
    const int lane = tid & 31;

    if (tid == 0) {
        int di = dsidx[b];
        float sigma = sigmas[di] * sf[b];
        float inv2s2 = 0.5f / (sigma * sigma);
        float s = 0.f;
        for (int k = 0; k < KTAPS; k++) {
            float d = (float)(k - PAD);
            float e = expf(-d * d * inv2s2);
            s_kern[k] = e;
            s += e;
        }
        float inv = 1.f / s;
        for (int k = 0; k < KTAPS; k++) s_kern[k] *= inv;
        float m = 0.f;
        for (int j = 0; j < n_ds; j++) m += pss[j];
        m /= (float)n_ds;
        s_scal[0] = expf(pss[di] - m);   // priority scaling
        s_scal[1] = cbws[di];            // center bias weight
    }

    // Load readout tile (B,1,96,128) -> smem (stride-129 rows)
    const float* rp = readout + b * SH * SW;
    for (int i = tid; i < SH * SW; i += 512)
        s_in[(i >> 7) * SSTRIDE + (i & 127)] = rp[i];
    __syncthreads();

    // ---- Vertical pass: thread = (col, 8-row block), sliding register window ----
    for (int t = tid; t < SW * (SH / 8); t += 512) {
        int col = t & 127;
        int r0  = (t >> 7) * 8;
        float w[8], acc[8];
        #pragma unroll
        for (int j = 0; j < 8; j++) {
            int rr = r0 - PAD + j;
            rr = rr < 0 ? 0 : rr;                 // high clamp impossible here
            w[j] = s_in[rr * SSTRIDE + col];
            acc[j] = 0.f;
        }
        #pragma unroll
        for (int k = 0; k < KTAPS; k++) {
            float tap = s_kern[k];
            #pragma unroll
            for (int j = 0; j < 8; j++) acc[j] = fmaf(tap, w[j], acc[j]);
            if (k < KTAPS - 1) {
                #pragma unroll
                for (int j = 0; j < 7; j++) w[j] = w[j + 1];
                int rr = r0 + k - 16;            // next window tail: r0+(k+1)-24+7
                rr = rr < 0 ? 0 : (rr > SH - 1 ? SH - 1 : rr);
                w[7] = s_in[rr * SSTRIDE + col];
            }
        }
        #pragma unroll
        for (int j = 0; j < 8; j++) s_tmp[(r0 + j) * SSTRIDE + col] = acc[j];
    }
    __syncthreads();

    // ---- Horizontal pass: warp = (32 rows x one 8-col block); lane = row ----
    // stride-129 rows => lane*129 + c spreads over all 32 banks: conflict-free.
    float prio = s_scal[0], cbw = s_scal[1];
    const float* cbp = centerbias + (size_t)b * BH * BW;
    float lmax = -INFINITY;

    for (int wt = wid; wt < (SH / 32) * (SW / 8); wt += 16) {
        int rg  = wt >> 4;          // 0..2
        int cbk = wt & 15;          // 0..15
        int row = rg * 32 + lane;
        int c0  = cbk * 8;
        const float* trow = s_tmp + row * SSTRIDE;
        float w[8], acc[8];
        #pragma unroll
        for (int j = 0; j < 8; j++) {
            int cc = c0 - PAD + j;
            cc = cc < 0 ? 0 : cc;
            w[j] = trow[cc];
            acc[j] = 0.f;
        }
        #pragma unroll
        for (int k = 0; k < KTAPS; k++) {
            float tap = s_kern[k];
            #pragma unroll
            for (int j = 0; j < 8; j++) acc[j] = fmaf(tap, w[j], acc[j]);
            if (k < KTAPS - 1) {
                #pragma unroll
                for (int j = 0; j < 7; j++) w[j] = w[j + 1];
                int cc = c0 + k - 16;
                cc = cc < 0 ? 0 : (cc > SW - 1 ? SW - 1 : cc);
                w[7] = trow[cc];
            }
        }
        // add center-bias sample (exact stride-8 nearest downsample) and stash
        const float* cbrow = cbp + (size_t)(row * 8) * BW;
        #pragma unroll
        for (int j = 0; j < 8; j++) {
            float v = prio * acc[j] + cbw * cbrow[(c0 + j) * 8];
            s_in[row * SSTRIDE + c0 + j] = v;
            lmax = fmaxf(lmax, v);
        }
    }

    // ---- Block logsumexp over the 96x128 values ----
    __syncthreads();
    #pragma unroll
    for (int o = 16; o > 0; o >>= 1) lmax = fmaxf(lmax, __shfl_xor_sync(0xFFFFFFFFu, lmax, o));
    if (lane == 0) s_red[wid] = lmax;
    __syncthreads();
    if (tid == 0) {
        float m = s_red[0];
        for (int i = 1; i < 16; i++) m = fmaxf(m, s_red[i]);
        s_scal[2] = m;
    }
    __syncthreads();
    float bmax = s_scal[2];

    float lsum = 0.f;
    float* outp = d_small + b * SH * SW;
    for (int i = tid; i < SH * SW; i += 512) {
        float v = s_in[(i >> 7) * SSTRIDE + (i & 127)];
        outp[i] = v;
        lsum += expf(v - bmax);
    }
    #pragma unroll
    for (int o = 16; o > 0; o >>= 1) lsum += __shfl_xor_sync(0xFFFFFFFFu, lsum, o);
    __syncthreads();            // s_red reuse: all prior reads complete
    if (lane == 0) s_red[wid] = lsum;
    __syncthreads();
    if (tid == 0) {
        float s = 0.f;
        for (int i = 0; i < 16; i++) s += s_red[i];
        // big-grid lse = small-grid lse + log(64)  (exact 8x8 replication)
        d_lse[b] = bmax + logf(s) + 4.1588830833596715f;
    }
}

// Expand small (96x128) to big (768x1024) with 8x8 nearest replication,
// subtracting the per-batch logsumexp. One thread -> 8 consecutive floats.
__global__ __launch_bounds__(256)
void write_kernel(float* __restrict__ out)
{
    int idx = blockIdx.x * 256 + threadIdx.x;       // 0 .. 32*768*128-1
    int b   = idx / (BH * (BW / 8));                // / 98304
    int rem = idx - b * (BH * (BW / 8));
    int r   = rem >> 7;
    int c8  = rem & 127;
    float v = d_small[b * SH * SW + (r >> 3) * SW + c8] - d_lse[b];
    float4 vv = make_float4(v, v, v, v);
    float4* p = (float4*)(out + (size_t)b * BH * BW + (size_t)r * BW + c8 * 8);
    p[0] = vv;
    p[1] = vv;
}

extern "C" void kernel_launch(void* const* d_in, const int* in_sizes, int n_in,
                              void* d_out, int out_size)
{
    const float* readout    = (const float*)d_in[0];
    const float* centerbias = (const float*)d_in[1];
    const float* sf         = (const float*)d_in[2];
    const int*   dsidx      = (const int*)  d_in[3];
    const float* sigmas     = (const float*)d_in[4];
    const float* cbws       = (const float*)d_in[5];
    const float* pss        = (const float*)d_in[6];
    int n_ds = in_sizes[4];

    const int smem_bytes = (2 * SH * SSTRIDE + 64 + 32 + 8) * (int)sizeof(float);
    cudaFuncSetAttribute(blur_kernel, cudaFuncAttributeMaxDynamicSharedMemorySize, smem_bytes);

    blur_kernel<<<BATCH, 512, smem_bytes>>>(readout, centerbias, sf, dsidx,
                                            sigmas, cbws, pss, n_ds);

    int total8 = BATCH * BH * (BW / 8);            // 3,145,728
    write_kernel<<<total8 / 256, 256>>>((float*)d_out);
}

// round 6
// speedup vs baseline: 1.3787x; 1.3787x over previous
#include <cuda_runtime.h>
#include <stdint.h>
#include <math.h>

#define BATCH 32
#define SH 96
#define SW 128
#define BH 768
#define BW 1024
#define KTAPS 49
#define PAD 24
#define SSTRIDE 129          // padded smem row stride -> conflict-free column access
#define STRIPES 3
#define SROWS 32             // rows per stripe
#define LROWS 80             // SROWS + 2*PAD halo rows loaded
#define LOG64 4.1588830833596715f

__device__ float d_small[BATCH * SH * SW];
__device__ float d_partial[BATCH * STRIPES];

// grid (STRIPES, BATCH), 256 threads. Stripe of 32 output rows per block.
__global__ __launch_bounds__(256, 1)
void blur_kernel(const float* __restrict__ readout,
                 const float* __restrict__ centerbias,
                 const float* __restrict__ sf,
                 const int*   __restrict__ dsidx,
                 const float* __restrict__ sigmas,
                 const float* __restrict__ cbws,
                 const float* __restrict__ pss,
                 int n_ds)
{
    extern __shared__ float smem[];
    float* s_in   = smem;                       // LROWS * SSTRIDE
    float* s_tmp  = s_in + LROWS * SSTRIDE;     // SROWS * SSTRIDE
    float* s_kern = s_tmp + SROWS * SSTRIDE;    // 64 (49 used)
    float* s_red  = s_kern + 64;                // 8
    float* s_scal = s_red + 8;                  // [0]=prio [1]=cbw

    const int stripe = blockIdx.x;
    const int b      = blockIdx.y;
    const int r0     = stripe * SROWS;
    const int tid    = threadIdx.x;
    const int wid    = tid >> 5;
    const int lane   = tid & 31;

    // kernel taps: threads 0..48 in parallel, thread 0 does scalars
    if (tid < KTAPS) {
        int di = dsidx[b];
        float sigma = sigmas[di] * sf[b];
        float inv2s2 = 0.5f / (sigma * sigma);
        float d = (float)(tid - PAD);
        s_kern[tid] = expf(-d * d * inv2s2);
        if (tid == 0) {
            float m = 0.f;
            for (int j = 0; j < n_ds; j++) m += pss[j];
            m /= (float)n_ds;
            s_scal[0] = expf(pss[di] - m);   // priority scaling
            s_scal[1] = cbws[di];            // center bias weight
        }
    }
    __syncthreads();
    // Normalize taps IN PLACE so the normalized kernel is used by BOTH
    // separable passes. Race-free: only thread 0 touches s_kern here, and
    // all other reads of s_kern occur after the next __syncthreads().
    if (tid == 0) {
        float s = 0.f;
        for (int k = 0; k < KTAPS; k++) s += s_kern[k];
        float inv = 1.f / s;
        for (int k = 0; k < KTAPS; k++) s_kern[k] *= inv;
    }

    // Load input rows [r0-24, r0+56) with edge clamp baked in.
    const float* rp = readout + b * SH * SW;
    for (int i = tid; i < LROWS * SW; i += 256) {
        int jr = i >> 7;
        int g  = r0 - PAD + jr;
        g = g < 0 ? 0 : (g > SH - 1 ? SH - 1 : g);
        s_in[jr * SSTRIDE + (i & 127)] = rp[g * SW + (i & 127)];
    }
    __syncthreads();

    // ---- Vertical pass: no clamping needed (halo in smem). task=(col, 8-row grp)
    for (int t = tid; t < SW * (SROWS / 8); t += 256) {
        int col = t & 127;
        int lr0 = (t >> 7) * 8;
        float w[8], acc[8];
        #pragma unroll
        for (int j = 0; j < 8; j++) {
            w[j] = s_in[(lr0 + j) * SSTRIDE + col];
            acc[j] = 0.f;
        }
        #pragma unroll
        for (int k = 0; k < KTAPS; k++) {
            float tap = s_kern[k];
            #pragma unroll
            for (int j = 0; j < 8; j++) acc[j] = fmaf(tap, w[j], acc[j]);
            if (k < KTAPS - 1) {
                #pragma unroll
                for (int j = 0; j < 7; j++) w[j] = w[j + 1];
                w[7] = s_in[(lr0 + k + 8) * SSTRIDE + col];
            }
        }
        #pragma unroll
        for (int j = 0; j < 8; j++) s_tmp[(lr0 + j) * SSTRIDE + col] = acc[j];
    }
    __syncthreads();

    // ---- Horizontal pass: task=(row 0..31, colgroup 0..15); lanes span rows.
    float prio = s_scal[0], cbw = s_scal[1];
    const float* cbp = centerbias + (size_t)b * BH * BW;
    float lsum = 0.f;

    for (int t = tid; t < SROWS * (SW / 8); t += 256) {
        int lr = t & 31;
        int c0 = (t >> 5) * 8;
        const float* trow = s_tmp + lr * SSTRIDE;
        float w[8], acc[8];
        #pragma unroll
        for (int j = 0; j < 8; j++) {
            int cc = c0 - PAD + j;
            cc = cc < 0 ? 0 : cc;
            w[j] = trow[cc];
            acc[j] = 0.f;
        }
        #pragma unroll
        for (int k = 0; k < KTAPS; k++) {
            float tap = s_kern[k];
            #pragma unroll
            for (int j = 0; j < 8; j++) acc[j] = fmaf(tap, w[j], acc[j]);
            if (k < KTAPS - 1) {
                #pragma unroll
                for (int j = 0; j < 7; j++) w[j] = w[j + 1];
                int cc = c0 + k - 16;
                cc = cc < 0 ? 0 : (cc > SW - 1 ? SW - 1 : cc);
                w[7] = trow[cc];
            }
        }
        int grow = r0 + lr;
        const float* cbrow = cbp + (size_t)(grow * 8) * BW;
        float* outp = d_small + b * SH * SW + grow * SW + c0;
        #pragma unroll
        for (int j = 0; j < 8; j++) {
            float v = prio * acc[j] + cbw * cbrow[(c0 + j) * 8];
            outp[j] = v;
            lsum += expf(v);        // values are O(1); no max shift needed
        }
    }

    // block-reduce partial sum of exp
    #pragma unroll
    for (int o = 16; o > 0; o >>= 1) lsum += __shfl_xor_sync(0xFFFFFFFFu, lsum, o);
    if (lane == 0) s_red[wid] = lsum;
    __syncthreads();
    if (tid == 0) {
        float s = 0.f;
        for (int i = 0; i < 8; i++) s += s_red[i];
        d_partial[b * STRIPES + stripe] = s;
    }
}

// grid (SH, BATCH), 128 threads. Build one replicated 4KB row in smem, then
// 8x 4KB TMA 1D bulk stores (SMEM -> L2 direct, bypassing L1/STG path).
__global__ __launch_bounds__(128, 8)
void write_kernel(float* __restrict__ out)
{
    __shared__ __align__(16) float s_row[BW];
    __shared__ float s_lse;

    const int rs  = blockIdx.x;      // small row 0..95
    const int b   = blockIdx.y;
    const int tid = threadIdx.x;

    unsigned int saddr;
    asm("{ .reg .u64 t; cvta.to.shared.u64 t, %1; cvt.u32.u64 %0, t; }"
        : "=r"(saddr) : "l"(s_row));

    if (tid == 0) {
        float p = d_partial[b * STRIPES + 0] + d_partial[b * STRIPES + 1]
                + d_partial[b * STRIPES + 2];
        s_lse = logf(p) + LOG64;
    }
    __syncthreads();

    float v = d_small[b * SH * SW + rs * SW + tid] - s_lse;
    float4 vv = make_float4(v, v, v, v);
    float4* sp = (float4*)(s_row + tid * 8);
    sp[0] = vv;
    sp[1] = vv;

    // All generic-proxy smem writes complete at the barrier; THEN the issuing
    // thread fences them into the async proxy before the TMA bulk store reads.
    __syncthreads();

    if (tid == 0) {
        asm volatile("fence.proxy.async.shared::cta;" ::: "memory");
        float* gbase = out + (size_t)b * BH * BW + (size_t)(rs * 8) * BW;
        #pragma unroll
        for (int i = 0; i < 8; i++) {
            asm volatile(
                "cp.async.bulk.global.shared::cta.bulk_group [%0], [%1], %2;"
                :: "l"(gbase + (size_t)i * BW), "r"(saddr), "n"(BW * 4)
                : "memory");
        }
        asm volatile("cp.async.bulk.commit_group;" ::: "memory");
        asm volatile("cp.async.bulk.wait_group 0;" ::: "memory");
    }
}

extern "C" void kernel_launch(void* const* d_in, const int* in_sizes, int n_in,
                              void* d_out, int out_size)
{
    const float* readout    = (const float*)d_in[0];
    const float* centerbias = (const float*)d_in[1];
    const float* sf         = (const float*)d_in[2];
    const int*   dsidx      = (const int*)  d_in[3];
    const float* sigmas     = (const float*)d_in[4];
    const float* cbws       = (const float*)d_in[5];
    const float* pss        = (const float*)d_in[6];
    int n_ds = in_sizes[4];

    const int smem_bytes = ((LROWS + SROWS) * SSTRIDE + 64 + 8 + 8) * (int)sizeof(float);
    cudaFuncSetAttribute(blur_kernel, cudaFuncAttributeMaxDynamicSharedMemorySize, smem_bytes);

    blur_kernel<<<dim3(STRIPES, BATCH), 256, smem_bytes>>>(
        readout, centerbias, sf, dsidx, sigmas, cbws, pss, n_ds);

    write_kernel<<<dim3(SH, BATCH), 128>>>((float*)d_out);
}

// round 8
// speedup vs baseline: 1.4493x; 1.0512x over previous
#include <cuda_runtime.h>
#include <stdint.h>
#include <math.h>

#define BATCH 32
#define SH 96
#define SW 128
#define BH 768
#define BW 1024
#define KTAPS 49
#define PAD 24
#define SSTRIDE 129          // padded smem row stride -> conflict-free column access
#define STRIPES 4
#define SROWS 24             // rows per stripe
#define LROWS 72             // SROWS + 2*PAD halo rows loaded
#define NTHR 384
#define LOG64 4.1588830833596715f
#define WROWS 4              // small rows per writer block

__device__ float d_small[BATCH * SH * SW];
__device__ float d_partial[BATCH * STRIPES];

// grid (STRIPES, BATCH), 384 threads. Stripe of 24 output rows per block.
__global__ __launch_bounds__(NTHR, 1)
void blur_kernel(const float* __restrict__ readout,
                 const float* __restrict__ centerbias,
                 const float* __restrict__ sf,
                 const int*   __restrict__ dsidx,
                 const float* __restrict__ sigmas,
                 const float* __restrict__ cbws,
                 const float* __restrict__ pss,
                 int n_ds)
{
    extern __shared__ float smem[];
    float* s_in   = smem;                       // LROWS * SSTRIDE
    float* s_tmp  = s_in + LROWS * SSTRIDE;     // SROWS * SSTRIDE
    float* s_kern = s_tmp + SROWS * SSTRIDE;    // 64 (49 used)
    float* s_red  = s_kern + 64;                // 12 used
    float* s_scal = s_red + 16;                 // [0]=prio [1]=cbw

    const int stripe = blockIdx.x;
    const int b      = blockIdx.y;
    const int r0     = stripe * SROWS;
    const int tid    = threadIdx.x;
    const int wid    = tid >> 5;
    const int lane   = tid & 31;

    // kernel taps: threads 0..48 in parallel, thread 0 does scalars
    if (tid < KTAPS) {
        int di = dsidx[b];
        float sigma = sigmas[di] * sf[b];
        float inv2s2 = 0.5f / (sigma * sigma);
        float d = (float)(tid - PAD);
        s_kern[tid] = expf(-d * d * inv2s2);
        if (tid == 0) {
            float m = 0.f;
            for (int j = 0; j < n_ds; j++) m += pss[j];
            m /= (float)n_ds;
            s_scal[0] = expf(pss[di] - m);   // priority scaling
            s_scal[1] = cbws[di];            // center bias weight
        }
    }
    __syncthreads();
    // Normalize taps IN PLACE (both separable passes use normalized taps).
    if (tid == 0) {
        float s = 0.f;
        for (int k = 0; k < KTAPS; k++) s += s_kern[k];
        float inv = 1.f / s;
        for (int k = 0; k < KTAPS; k++) s_kern[k] *= inv;
    }

    // Load input rows [r0-24, r0+48) with edge clamp baked in.
    const float* rp = readout + b * SH * SW;
    for (int i = tid; i < LROWS * SW; i += NTHR) {
        int jr = i >> 7;
        int g  = r0 - PAD + jr;
        g = g < 0 ? 0 : (g > SH - 1 ? SH - 1 : g);
        s_in[jr * SSTRIDE + (i & 127)] = rp[g * SW + (i & 127)];
    }
    __syncthreads();

    // ---- Vertical pass: halo in smem so no clamping. 384 tasks = 1/thread.
    {
        int t   = tid;                 // t < SW * (SROWS/8) = 384
        int col = t & 127;
        int lr0 = (t >> 7) * 8;        // 0, 8, 16
        float w[8], acc[8];
        #pragma unroll
        for (int j = 0; j < 8; j++) {
            w[j] = s_in[(lr0 + j) * SSTRIDE + col];
            acc[j] = 0.f;
        }
        #pragma unroll
        for (int k = 0; k < KTAPS; k++) {
            float tap = s_kern[k];
            #pragma unroll
            for (int j = 0; j < 8; j++) acc[j] = fmaf(tap, w[j], acc[j]);
            if (k < KTAPS - 1) {
                #pragma unroll
                for (int j = 0; j < 7; j++) w[j] = w[j + 1];
                w[7] = s_in[(lr0 + k + 8) * SSTRIDE + col];
            }
        }
        #pragma unroll
        for (int j = 0; j < 8; j++) s_tmp[(lr0 + j) * SSTRIDE + col] = acc[j];
    }
    __syncthreads();

    // ---- Horizontal pass: 384 tasks = 1/thread. lr = t % 24, colgroup = t/24.
    float prio = s_scal[0], cbw = s_scal[1];
    const float* cbp = centerbias + (size_t)b * BH * BW;
    float lsum = 0.f;

    {
        int t  = tid;
        int lr = t % SROWS;
        int c0 = (t / SROWS) * 8;
        const float* trow = s_tmp + lr * SSTRIDE;
        float w[8], acc[8];
        #pragma unroll
        for (int j = 0; j < 8; j++) {
            int cc = c0 - PAD + j;
            cc = cc < 0 ? 0 : cc;
            w[j] = trow[cc];
            acc[j] = 0.f;
        }
        #pragma unroll
        for (int k = 0; k < KTAPS; k++) {
            float tap = s_kern[k];
            #pragma unroll
            for (int j = 0; j < 8; j++) acc[j] = fmaf(tap, w[j], acc[j]);
            if (k < KTAPS - 1) {
                #pragma unroll
                for (int j = 0; j < 7; j++) w[j] = w[j + 1];
                int cc = c0 + k - 16;
                cc = cc < 0 ? 0 : (cc > SW - 1 ? SW - 1 : cc);
                w[7] = trow[cc];
            }
        }
        int grow = r0 + lr;
        const float* cbrow = cbp + (size_t)(grow * 8) * BW;
        float* outp = d_small + b * SH * SW + grow * SW + c0;
        #pragma unroll
        for (int j = 0; j < 8; j++) {
            float v = prio * acc[j] + cbw * cbrow[(c0 + j) * 8];
            outp[j] = v;
            lsum += __expf(v);      // values O(1); no max shift needed
        }
    }

    // block-reduce partial sum of exp (12 warps)
    #pragma unroll
    for (int o = 16; o > 0; o >>= 1) lsum += __shfl_xor_sync(0xFFFFFFFFu, lsum, o);
    if (lane == 0) s_red[wid] = lsum;
    __syncthreads();
    if (tid == 0) {
        float s = 0.f;
        for (int i = 0; i < NTHR / 32; i++) s += s_red[i];
        d_partial[b * STRIPES + stripe] = s;
    }
}

// grid (SH/WROWS, BATCH), 128 threads. Build WROWS replicated 4KB rows in smem,
// then 8*WROWS TMA 1D bulk stores with a single drain at the end.
__global__ __launch_bounds__(128, 8)
void write_kernel(float* __restrict__ out)
{
    __shared__ __align__(16) float s_rows[WROWS][BW];
    __shared__ float s_lse;

    const int rs0 = blockIdx.x * WROWS;   // first small row
    const int b   = blockIdx.y;
    const int tid = threadIdx.x;

    if (tid == 0) {
        float p = 0.f;
        #pragma unroll
        for (int i = 0; i < STRIPES; i++) p += d_partial[b * STRIPES + i];
        s_lse = logf(p) + LOG64;
    }
    __syncthreads();
    float lse = s_lse;

    #pragma unroll
    for (int r = 0; r < WROWS; r++) {
        float v = d_small[b * SH * SW + (rs0 + r) * SW + tid] - lse;
        float4 vv = make_float4(v, v, v, v);
        float4* sp = (float4*)(&s_rows[r][tid * 8]);
        sp[0] = vv;
        sp[1] = vv;
    }

    __syncthreads();

    if (tid == 0) {
        asm volatile("fence.proxy.async.shared::cta;" ::: "memory");
        #pragma unroll
        for (int r = 0; r < WROWS; r++) {
            unsigned int saddr;
            asm("{ .reg .u64 t; cvta.to.shared.u64 t, %1; cvt.u32.u64 %0, t; }"
                : "=r"(saddr) : "l"(&s_rows[r][0]));
            float* gbase = out + (size_t)b * BH * BW + (size_t)((rs0 + r) * 8) * BW;
            #pragma unroll
            for (int i = 0; i < 8; i++) {
                asm volatile(
                    "cp.async.bulk.global.shared::cta.bulk_group [%0], [%1], %2;"
                    :: "l"(gbase + (size_t)i * BW), "r"(saddr), "n"(BW * 4)
                    : "memory");
            }
        }
        asm volatile("cp.async.bulk.commit_group;" ::: "memory");
        asm volatile("cp.async.bulk.wait_group 0;" ::: "memory");
    }
}

extern "C" void kernel_launch(void* const* d_in, const int* in_sizes, int n_in,
                              void* d_out, int out_size)
{
    const float* readout    = (const float*)d_in[0];
    const float* centerbias = (const float*)d_in[1];
    const float* sf         = (const float*)d_in[2];
    const int*   dsidx      = (const int*)  d_in[3];
    const float* sigmas     = (const float*)d_in[4];
    const float* cbws       = (const float*)d_in[5];
    const float* pss        = (const float*)d_in[6];
    int n_ds = in_sizes[4];

    const int smem_bytes = ((LROWS + SROWS) * SSTRIDE + 64 + 16 + 8) * (int)sizeof(float);
    cudaFuncSetAttribute(blur_kernel, cudaFuncAttributeMaxDynamicSharedMemorySize, smem_bytes);

    blur_kernel<<<dim3(STRIPES, BATCH), NTHR, smem_bytes>>>(
        readout, centerbias, sf, dsidx, sigmas, cbws, pss, n_ds);

    write_kernel<<<dim3(SH / WROWS, BATCH), 128>>>((float*)d_out);
}

// round 10
// speedup vs baseline: 1.5914x; 1.0981x over previous
#include <cuda_runtime.h>
#include <stdint.h>
#include <math.h>

#define BATCH 32
#define SH 96
#define SW 128
#define BH 768
#define BW 1024
#define KTAPS 49
#define PAD 24
#define SSTRIDE 129          // padded smem row stride -> conflict-free column access
#define STRIPES 4
#define SROWS 24             // rows per stripe
#define LROWS 72             // SROWS + 2*PAD halo rows loaded
#define NTHR 384
#define LOG64 4.1588830833596715f
#define WROWS 8              // small rows per writer block

__device__ float d_small[BATCH * SH * SW];
__device__ float d_partial[BATCH * STRIPES];

// grid (STRIPES, BATCH), 384 threads. Stripe of 24 output rows per block.
__global__ __launch_bounds__(NTHR, 1)
void blur_kernel(const float* __restrict__ readout,
                 const float* __restrict__ centerbias,
                 const float* __restrict__ sf,
                 const int*   __restrict__ dsidx,
                 const float* __restrict__ sigmas,
                 const float* __restrict__ cbws,
                 const float* __restrict__ pss,
                 int n_ds)
{
    extern __shared__ float smem[];
    float* s_in   = smem;                       // LROWS * SSTRIDE
    float* s_tmp  = s_in + LROWS * SSTRIDE;     // SROWS * SSTRIDE
    float* s_kern = s_tmp + SROWS * SSTRIDE;    // 64 (49 used)
    float* s_red  = s_kern + 64;                // 12 used
    float* s_scal = s_red + 16;                 // [0]=prio [1]=cbw

    const int stripe = blockIdx.x;
    const int b      = blockIdx.y;
    const int r0     = stripe * SROWS;
    const int tid    = threadIdx.x;
    const int wid    = tid >> 5;
    const int lane   = tid & 31;

    // ---- Prefetch centerbias gather for this thread's horizontal task.
    // Issued FIRST so the ~600cyc scattered-sector DRAM latency overlaps
    // taps + readout load + vertical pass. 8 independent LDGs.
    const int h_lr = tid % SROWS;               // horizontal-task row
    const int h_c0 = (tid / SROWS) * 8;         // horizontal-task col group
    const float* cbp = centerbias + (size_t)b * BH * BW
                     + (size_t)((r0 + h_lr) * 8) * BW;
    float cbv[8];
    #pragma unroll
    for (int j = 0; j < 8; j++) cbv[j] = __ldg(&cbp[(h_c0 + j) * 8]);

    // ---- Readout load into registers (24 independent LDGs), STS deferred.
    const float* rp = readout + b * SH * SW;
    float rin[24];
    #pragma unroll
    for (int j = 0; j < 24; j++) {
        int i  = tid + j * NTHR;
        int jr = i >> 7;
        int g  = r0 - PAD + jr;
        g = g < 0 ? 0 : (g > SH - 1 ? SH - 1 : g);
        rin[j] = __ldg(&rp[g * SW + (i & 127)]);
    }

    // kernel taps: threads 0..48 in parallel, thread 0 does scalars
    if (tid < KTAPS) {
        int di = dsidx[b];
        float sigma = sigmas[di] * sf[b];
        float inv2s2 = 0.5f / (sigma * sigma);
        float d = (float)(tid - PAD);
        s_kern[tid] = expf(-d * d * inv2s2);
        if (tid == 0) {
            float m = 0.f;
            for (int j = 0; j < n_ds; j++) m += pss[j];
            m /= (float)n_ds;
            s_scal[0] = expf(pss[di] - m);   // priority scaling
            s_scal[1] = cbws[di];            // center bias weight
        }
    }
    __syncthreads();
    // Normalize taps IN PLACE (both passes use normalized taps). Other threads
    // overlap this with their STS of the readout tile.
    if (tid == 0) {
        float s = 0.f;
        for (int k = 0; k < KTAPS; k++) s += s_kern[k];
        float inv = 1.f / s;
        for (int k = 0; k < KTAPS; k++) s_kern[k] *= inv;
    }
    #pragma unroll
    for (int j = 0; j < 24; j++) {
        int i = tid + j * NTHR;
        s_in[(i >> 7) * SSTRIDE + (i & 127)] = rin[j];
    }
    __syncthreads();

    // ---- Vertical pass: halo in smem so no clamping. 384 tasks = 1/thread.
    {
        int col = tid & 127;
        int lr0 = (tid >> 7) * 8;      // 0, 8, 16
        float w[8], acc[8];
        #pragma unroll
        for (int j = 0; j < 8; j++) {
            w[j] = s_in[(lr0 + j) * SSTRIDE + col];
            acc[j] = 0.f;
        }
        #pragma unroll
        for (int k = 0; k < KTAPS; k++) {
            float tap = s_kern[k];
            #pragma unroll
            for (int j = 0; j < 8; j++) acc[j] = fmaf(tap, w[j], acc[j]);
            if (k < KTAPS - 1) {
                #pragma unroll
                for (int j = 0; j < 7; j++) w[j] = w[j + 1];
                w[7] = s_in[(lr0 + k + 8) * SSTRIDE + col];
            }
        }
        #pragma unroll
        for (int j = 0; j < 8; j++) s_tmp[(lr0 + j) * SSTRIDE + col] = acc[j];
    }
    __syncthreads();

    // ---- Horizontal pass: 384 tasks = 1/thread (row h_lr, cols h_c0..+7).
    float prio = s_scal[0], cbw = s_scal[1];
    float lsum = 0.f;
    {
        const float* trow = s_tmp + h_lr * SSTRIDE;
        float w[8], acc[8];
        #pragma unroll
        for (int j = 0; j < 8; j++) {
            int cc = h_c0 - PAD + j;
            cc = cc < 0 ? 0 : cc;
            w[j] = trow[cc];
            acc[j] = 0.f;
        }
        #pragma unroll
        for (int k = 0; k < KTAPS; k++) {
            float tap = s_kern[k];
            #pragma unroll
            for (int j = 0; j < 8; j++) acc[j] = fmaf(tap, w[j], acc[j]);
            if (k < KTAPS - 1) {
                #pragma unroll
                for (int j = 0; j < 7; j++) w[j] = w[j + 1];
                int cc = h_c0 + k - 16;
                cc = cc < 0 ? 0 : (cc > SW - 1 ? SW - 1 : cc);
                w[7] = trow[cc];
            }
        }
        float* outp = d_small + b * SH * SW + (r0 + h_lr) * SW + h_c0;
        #pragma unroll
        for (int j = 0; j < 8; j++) {
            float v = prio * acc[j] + cbw * cbv[j];
            outp[j] = v;
            lsum += __expf(v);      // values O(1); no max shift needed
        }
    }

    // block-reduce partial sum of exp (12 warps)
    #pragma unroll
    for (int o = 16; o > 0; o >>= 1) lsum += __shfl_xor_sync(0xFFFFFFFFu, lsum, o);
    if (lane == 0) s_red[wid] = lsum;
    __syncthreads();
    if (tid == 0) {
        float s = 0.f;
        for (int i = 0; i < NTHR / 32; i++) s += s_red[i];
        d_partial[b * STRIPES + stripe] = s;
    }
}

// grid (SH/WROWS, BATCH), 128 threads. Build WROWS replicated 4KB rows in smem,
// then 8*WROWS TMA 1D bulk stores with a single drain at the end.
__global__ __launch_bounds__(128, 3)
void write_kernel(float* __restrict__ out)
{
    __shared__ __align__(16) float s_rows[WROWS][BW];
    __shared__ float s_lse;

    const int rs0 = blockIdx.x * WROWS;   // first small row
    const int b   = blockIdx.y;
    const int tid = threadIdx.x;

    if (tid == 0) {
        float p = 0.f;
        #pragma unroll
        for (int i = 0; i < STRIPES; i++) p += d_partial[b * STRIPES + i];
        s_lse = logf(p) + LOG64;
    }
    __syncthreads();
    float lse = s_lse;

    #pragma unroll
    for (int r = 0; r < WROWS; r++) {
        float v = d_small[b * SH * SW + (rs0 + r) * SW + tid] - lse;
        float4 vv = make_float4(v, v, v, v);
        float4* sp = (float4*)(&s_rows[r][tid * 8]);
        sp[0] = vv;
        sp[1] = vv;
    }

    __syncthreads();

    if (tid == 0) {
        asm volatile("fence.proxy.async.shared::cta;" ::: "memory");
        #pragma unroll
        for (int r = 0; r < WROWS; r++) {
            unsigned int saddr;
            asm("{ .reg .u64 t; cvta.to.shared.u64 t, %1; cvt.u32.u64 %0, t; }"
                : "=r"(saddr) : "l"(&s_rows[r][0]));
            float* gbase = out + (size_t)b * BH * BW + (size_t)((rs0 + r) * 8) * BW;
            #pragma unroll
            for (int i = 0; i < 8; i++) {
                asm volatile(
                    "cp.async.bulk.global.shared::cta.bulk_group [%0], [%1], %2;"
                    :: "l"(gbase + (size_t)i * BW), "r"(saddr), "n"(BW * 4)
                    : "memory");
            }
        }
        asm volatile("cp.async.bulk.commit_group;" ::: "memory");
        asm volatile("cp.async.bulk.wait_group 0;" ::: "memory");
    }
}

extern "C" void kernel_launch(void* const* d_in, const int* in_sizes, int n_in,
                              void* d_out, int out_size)
{
    const float* readout    = (const float*)d_in[0];
    const float* centerbias = (const float*)d_in[1];
    const float* sf         = (const float*)d_in[2];
    const int*   dsidx      = (const int*)  d_in[3];
    const float* sigmas     = (const float*)d_in[4];
    const float* cbws       = (const float*)d_in[5];
    const float* pss        = (const float*)d_in[6];
    int n_ds = in_sizes[4];

    const int smem_bytes = ((LROWS + SROWS) * SSTRIDE + 64 + 16 + 8) * (int)sizeof(float);
    cudaFuncSetAttribute(blur_kernel, cudaFuncAttributeMaxDynamicSharedMemorySize, smem_bytes);

    blur_kernel<<<dim3(STRIPES, BATCH), NTHR, smem_bytes>>>(
        readout, centerbias, sf, dsidx, sigmas, cbws, pss, n_ds);

    write_kernel<<<dim3(SH / WROWS, BATCH), 128>>>((float*)d_out);
}

// round 12
// speedup vs baseline: 1.7370x; 1.0915x over previous
#include <cuda_runtime.h>
#include <stdint.h>
#include <math.h>

#define BATCH 32
#define SH 96
#define SW 128
#define BH 768
#define BW 1024
#define KTAPS 49
#define PAD 24
#define SSTRIDE 129          // padded smem row stride -> conflict-free column access
#define STRIPES 4
#define SROWS 24             // rows per stripe
#define LROWS 72             // SROWS + 2*PAD halo rows loaded
#define NTHR 384
#define LOG64 4.1588830833596715f
#define CHUNK 4              // small rows staged per TMA chunk
#define NCHUNK (SROWS / CHUNK)

__device__ float d_partial[BATCH * STRIPES];
__device__ int   d_cnt[BATCH];    // stripes arrived (reset by last-done CTA)
__device__ int   d_done[BATCH];   // write phases finished (reset by last-done CTA)

// grid (STRIPES, BATCH) = 128 CTAs (single wave, all resident), 384 threads.
// Phase 1: separable blur of a 24-row stripe (outputs kept in smem).
// Phase 2: intra-batch sync via atomics, local LSE, 8x8 expansion via
//          double-buffered TMA bulk stores.
__global__ __launch_bounds__(NTHR, 1)
void fused_kernel(float* __restrict__ out,
                  const float* __restrict__ readout,
                  const float* __restrict__ centerbias,
                  const float* __restrict__ sf,
                  const int*   __restrict__ dsidx,
                  const float* __restrict__ sigmas,
                  const float* __restrict__ cbws,
                  const float* __restrict__ pss,
                  int n_ds)
{
    extern __shared__ float smem[];
    float* s_in   = smem;                 // 9288 fl: input tile; reused as staging
    float* s_tmp  = smem + LROWS * SSTRIDE;          // 3096 fl: vertical result
    float* s_out  = s_tmp + SROWS * SSTRIDE;         // 3096 fl: final small values
    float* s_kern = s_out + SROWS * SSTRIDE;         // 64 (49 used)
    float* s_red  = s_kern + 64;                     // 12 used
    float* s_scal = s_red + 16;                      // [0]=prio [1]=cbw [3]=lse

    const int stripe = blockIdx.x;
    const int b      = blockIdx.y;
    const int r0     = stripe * SROWS;
    const int tid    = threadIdx.x;
    const int wid    = tid >> 5;
    const int lane   = tid & 31;

    // ---- Prefetch centerbias gather (scattered DRAM latency overlaps everything)
    const int h_lr = tid % SROWS;
    const int h_c0 = (tid / SROWS) * 8;
    const float* cbp = centerbias + (size_t)b * BH * BW
                     + (size_t)((r0 + h_lr) * 8) * BW;
    float cbv[8];
    #pragma unroll
    for (int j = 0; j < 8; j++) cbv[j] = __ldg(&cbp[(h_c0 + j) * 8]);

    // ---- Readout tile into registers (24 independent LDGs), STS deferred.
    const float* rp = readout + b * SH * SW;
    float rin[24];
    #pragma unroll
    for (int j = 0; j < 24; j++) {
        int i  = tid + j * NTHR;
        int jr = i >> 7;
        int g  = r0 - PAD + jr;
        g = g < 0 ? 0 : (g > SH - 1 ? SH - 1 : g);
        rin[j] = __ldg(&rp[g * SW + (i & 127)]);
    }

    // kernel taps + scalars
    if (tid < KTAPS) {
        int di = dsidx[b];
        float sigma = sigmas[di] * sf[b];
        float inv2s2 = 0.5f / (sigma * sigma);
        float d = (float)(tid - PAD);
        s_kern[tid] = expf(-d * d * inv2s2);
        if (tid == 0) {
            float m = 0.f;
            for (int j = 0; j < n_ds; j++) m += pss[j];
            m /= (float)n_ds;
            s_scal[0] = expf(pss[di] - m);
            s_scal[1] = cbws[di];
        }
    }
    __syncthreads();
    if (tid == 0) {       // normalize taps in place (both passes use them)
        float s = 0.f;
        for (int k = 0; k < KTAPS; k++) s += s_kern[k];
        float inv = 1.f / s;
        for (int k = 0; k < KTAPS; k++) s_kern[k] *= inv;
    }
    #pragma unroll
    for (int j = 0; j < 24; j++) {
        int i = tid + j * NTHR;
        s_in[(i >> 7) * SSTRIDE + (i & 127)] = rin[j];
    }
    __syncthreads();

    // ---- Vertical pass (halo in smem, no clamping). 1 task/thread.
    {
        int col = tid & 127;
        int lr0 = (tid >> 7) * 8;
        float w[8], acc[8];
        #pragma unroll
        for (int j = 0; j < 8; j++) {
            w[j] = s_in[(lr0 + j) * SSTRIDE + col];
            acc[j] = 0.f;
        }
        #pragma unroll
        for (int k = 0; k < KTAPS; k++) {
            float tap = s_kern[k];
            #pragma unroll
            for (int j = 0; j < 8; j++) acc[j] = fmaf(tap, w[j], acc[j]);
            if (k < KTAPS - 1) {
                #pragma unroll
                for (int j = 0; j < 7; j++) w[j] = w[j + 1];
                w[7] = s_in[(lr0 + k + 8) * SSTRIDE + col];
            }
        }
        #pragma unroll
        for (int j = 0; j < 8; j++) s_tmp[(lr0 + j) * SSTRIDE + col] = acc[j];
    }
    __syncthreads();

    // ---- Horizontal pass -> s_out (stays in smem; no d_small round-trip).
    float prio = s_scal[0], cbw = s_scal[1];
    float lsum = 0.f;
    {
        const float* trow = s_tmp + h_lr * SSTRIDE;
        float w[8], acc[8];
        #pragma unroll
        for (int j = 0; j < 8; j++) {
            int cc = h_c0 - PAD + j;
            cc = cc < 0 ? 0 : cc;
            w[j] = trow[cc];
            acc[j] = 0.f;
        }
        #pragma unroll
        for (int k = 0; k < KTAPS; k++) {
            float tap = s_kern[k];
            #pragma unroll
            for (int j = 0; j < 8; j++) acc[j] = fmaf(tap, w[j], acc[j]);
            if (k < KTAPS - 1) {
                #pragma unroll
                for (int j = 0; j < 7; j++) w[j] = w[j + 1];
                int cc = h_c0 + k - 16;
                cc = cc < 0 ? 0 : (cc > SW - 1 ? SW - 1 : cc);
                w[7] = trow[cc];
            }
        }
        #pragma unroll
        for (int j = 0; j < 8; j++) {
            float v = prio * acc[j] + cbw * cbv[j];
            s_out[h_lr * SSTRIDE + h_c0 + j] = v;
            lsum += __expf(v);
        }
    }

    // ---- Publish stripe partial, spin for batch completion, compute LSE.
    #pragma unroll
    for (int o = 16; o > 0; o >>= 1) lsum += __shfl_xor_sync(0xFFFFFFFFu, lsum, o);
    if (lane == 0) s_red[wid] = lsum;
    __syncthreads();
    if (tid == 0) {
        float s = 0.f;
        for (int i = 0; i < NTHR / 32; i++) s += s_red[i];
        d_partial[b * STRIPES + stripe] = s;
        __threadfence();
        atomicAdd(&d_cnt[b], 1);
        volatile int* vc = &d_cnt[b];
        while (*vc < STRIPES) __nanosleep(100);
        __threadfence();
        float p = d_partial[b * STRIPES + 0] + d_partial[b * STRIPES + 1]
                + d_partial[b * STRIPES + 2] + d_partial[b * STRIPES + 3];
        s_scal[3] = logf(p) + LOG64;
    }
    __syncthreads();
    const float lse = s_scal[3];

    // ---- Write phase: 24 small rows -> 192 big rows, double-buffered TMA.
    // Staging reuses s_in: two 4-row buffers (16 KB each, 16B-aligned offsets).
    for (int c = 0; c < NCHUNK; c++) {
        if (tid == 0)
            asm volatile("cp.async.bulk.wait_group 1;" ::: "memory"); // buf free
        __syncthreads();
        float* buf = s_in + (c & 1) * (CHUNK * BW);
        for (int i4 = tid; i4 < CHUNK * BW / 4; i4 += NTHR) {
            int row = i4 >> 8;            // /256 float4 per big row
            int ii  = i4 & 255;
            int sc  = ii >> 1;            // small col (each float4 is one sc)
            float v = s_out[(c * CHUNK + row) * SSTRIDE + sc] - lse;
            ((float4*)buf)[i4] = make_float4(v, v, v, v);
        }
        __syncthreads();
        if (tid == 0) {
            asm volatile("fence.proxy.async.shared::cta;" ::: "memory");
            #pragma unroll
            for (int row = 0; row < CHUNK; row++) {
                unsigned int saddr;
                asm("{ .reg .u64 t; cvta.to.shared.u64 t, %1; cvt.u32.u64 %0, t; }"
                    : "=r"(saddr) : "l"(buf + row * BW));
                float* gbase = out + (size_t)b * BH * BW
                             + (size_t)((r0 + c * CHUNK + row) * 8) * BW;
                #pragma unroll
                for (int rep = 0; rep < 8; rep++) {
                    asm volatile(
                        "cp.async.bulk.global.shared::cta.bulk_group [%0], [%1], %2;"
                        :: "l"(gbase + (size_t)rep * BW), "r"(saddr), "n"(BW * 4)
                        : "memory");
                }
            }
            asm volatile("cp.async.bulk.commit_group;" ::: "memory");
        }
    }
    if (tid == 0)
        asm volatile("cp.async.bulk.wait_group 0;" ::: "memory");
    __syncthreads();

    // ---- Reset sync state for graph replay (last finisher per batch).
    if (tid == 0) {
        int old = atomicAdd(&d_done[b], 1);
        if (old == STRIPES - 1) {
            d_cnt[b]  = 0;
            d_done[b] = 0;
        }
    }
}

extern "C" void kernel_launch(void* const* d_in, const int* in_sizes, int n_in,
                              void* d_out, int out_size)
{
    const float* readout    = (const float*)d_in[0];
    const float* centerbias = (const float*)d_in[1];
    const float* sf         = (const float*)d_in[2];
    const int*   dsidx      = (const int*)  d_in[3];
    const float* sigmas     = (const float*)d_in[4];
    const float* cbws       = (const float*)d_in[5];
    const float* pss        = (const float*)d_in[6];
    int n_ds = in_sizes[4];

    const int smem_bytes =
        (LROWS * SSTRIDE + 2 * SROWS * SSTRIDE + 64 + 16 + 8) * (int)sizeof(float);
    cudaFuncSetAttribute(fused_kernel, cudaFuncAttributeMaxDynamicSharedMemorySize,
                         smem_bytes);

    fused_kernel<<<dim3(STRIPES, BATCH), NTHR, smem_bytes>>>(
        (float*)d_out, readout, centerbias, sf, dsidx, sigmas, cbws, pss, n_ds);
}